// round 12
// baseline (speedup 1.0000x reference)
#include <cuda_runtime.h>
#include <cstdint>

// out[t,:] = 1 / where(dmat[row(t),:]==0, BIG, dmat[row(t),:])
//   row(t) = venueid2coor[inputs_poi[t]]
// R11: tokens compacted in row-sorted order; one uniform CTA per
// (token, half-row segment). Duplicate-row reads hit L2 (adjacent CTAs);
// DRAM reads ~= unique rows. Caching loads for src, streaming stores for dst.

#define N_POI    10000
#define V_SIZE   20000
#define N_TOK    6400

#define SEGMENTS 2
#define SEG_VEC  1250        // float4 per segment (2500 total per row)
#define FULL_IT  4           // 4*256 = 1024 vectors
#define TAIL     226         // 1250 - 1024

__device__ int g_head[N_POI];
__device__ int g_next[N_TOK];
__device__ int g_tok[N_TOK];   // tokens in row-sorted order
__device__ int g_row[N_TOK];   // row for each entry
__device__ int g_cursor;
__device__ int g_poi_is64;
__device__ int g_v2c_is64;

__global__ void init_kernel(const unsigned int* poi, const unsigned int* v2c)
{
    int i = blockIdx.x * blockDim.x + threadIdx.x;
    if (i < N_POI) g_head[i] = -1;
    if (i == 0) {
        int poi64 = 1, v2c64 = 1;
        #pragma unroll
        for (int k = 1; k < 32; k += 2) {      // LE int64 small values -> odd words 0
            if (poi[k] != 0u) poi64 = 0;
            if (v2c[k] != 0u) v2c64 = 0;
        }
        g_poi_is64 = poi64;
        g_v2c_is64 = v2c64;
        g_cursor = 0;
    }
}

__global__ void build_lists_kernel(const void* __restrict__ venueid2coor,
                                   const void* __restrict__ inputs_poi,
                                   int n_tok)
{
    int t = blockIdx.x * blockDim.x + threadIdx.x;
    if (t >= n_tok) return;

    long long vid = g_poi_is64 ? ((const long long*)inputs_poi)[t]
                               : (long long)((const int*)inputs_poi)[t];
    if (vid < 0) vid = 0;
    if (vid >= V_SIZE) vid = V_SIZE - 1;

    long long row = g_v2c_is64 ? ((const long long*)venueid2coor)[vid]
                               : (long long)((const int*)venueid2coor)[vid];
    if (row < 0) row = 0;
    if (row >= N_POI) row = N_POI - 1;

    g_next[t] = atomicExch(&g_head[(int)row], t);
}

// One thread per row: emit this row's tokens contiguously (row-sorted order).
__global__ void compact_kernel()
{
    int r = blockIdx.x * blockDim.x + threadIdx.x;
    if (r >= N_POI) return;
    int t = g_head[r];
    if (t < 0) return;

    int cnt = 0;
    for (int tmp = t; tmp >= 0; tmp = g_next[tmp]) cnt++;
    int pos = atomicAdd(&g_cursor, cnt);
    for (int tmp = t; tmp >= 0; tmp = g_next[tmp]) {
        g_tok[pos] = tmp;
        g_row[pos] = r;
        pos++;
    }
}

__device__ __forceinline__ float4 xform(float4 v)
{
    const float BIG = 9999999.99f;
    float4 r;
    r.x = __frcp_rn(v.x == 0.0f ? BIG : v.x);
    r.y = __frcp_rn(v.y == 0.0f ? BIG : v.y);
    r.z = __frcp_rn(v.z == 0.0f ? BIG : v.z);
    r.w = __frcp_rn(v.w == 0.0f ? BIG : v.w);
    return r;
}

// grid = (N_TOK, SEGMENTS), block = 256. Every CTA does identical work.
__global__ void __launch_bounds__(256) stream_kernel(
    const float* __restrict__ dmat,
    float*       __restrict__ out,
    int n_tok)
{
    const int w = blockIdx.x;
    if (w >= n_tok) return;

    const int row   = g_row[w];            // uniform -> broadcast
    const int token = g_tok[w];
    const int tid = threadIdx.x;
    const int segbase = blockIdx.y * SEG_VEC;

    const float4* __restrict__ src =
        reinterpret_cast<const float4*>(dmat + (size_t)row * N_POI) + segbase;
    float4* __restrict__ dst =
        reinterpret_cast<float4*>(out + (size_t)token * N_POI) + segbase;

    // Caching loads: duplicate-row CTAs are adjacent in bid order, so repeat
    // reads of the same 40KB row hit L2. Streaming stores: output never re-read.
    float4 v[FULL_IT];
    #pragma unroll
    for (int k = 0; k < FULL_IT; k++)
        v[k] = __ldg(&src[tid + k * 256]);
    #pragma unroll
    for (int k = 0; k < FULL_IT; k++)
        __stcs(&dst[tid + k * 256], xform(v[k]));
    if (tid < TAIL) {
        float4 t4 = __ldg(&src[FULL_IT * 256 + tid]);
        __stcs(&dst[FULL_IT * 256 + tid], xform(t4));
    }
}

extern "C" void kernel_launch(void* const* d_in, const int* in_sizes, int n_in,
                              void* d_out, int out_size)
{
    const void*  venueid2coor = d_in[0];
    const void*  inputs_poi   = d_in[1];
    const float* dmat         = (const float*)d_in[2];
    float*       out          = (float*)d_out;

    int n_tok = in_sizes[1];
    if (n_tok > N_TOK) n_tok = N_TOK;

    init_kernel<<<(N_POI + 255) / 256, 256>>>((const unsigned int*)inputs_poi,
                                              (const unsigned int*)venueid2coor);
    build_lists_kernel<<<(n_tok + 255) / 256, 256>>>(venueid2coor, inputs_poi, n_tok);
    compact_kernel<<<(N_POI + 255) / 256, 256>>>();

    dim3 grid(n_tok, SEGMENTS);
    stream_kernel<<<grid, 256>>>(dmat, out, n_tok);
}